// round 1
// baseline (speedup 1.0000x reference)
#include <cuda_runtime.h>
#include <math.h>

#define B_SZ    4
#define T_SEQ   2048
#define C_DIM   768
#define QKV_DIM 2304
#define N_HEAD  12
#define HD      64
#define M_TOK   (B_SZ * T_SEQ)   // 8192

// Scratch (device globals: no allocation allowed in kernel_launch)
__device__ float g_h[M_TOK * C_DIM];       // LN output
__device__ float g_qkv[M_TOK * QKV_DIM];   // QKV
__device__ float g_att[M_TOK * C_DIM];     // attention output (pre-proj)

// ---------------------------------------------------------------------------
// LayerNorm: one block per row (768 cols), 256 threads x 3 elems
// ---------------------------------------------------------------------------
__global__ void ln_kernel(const float* __restrict__ x,
                          const float* __restrict__ g,
                          const float* __restrict__ b,
                          float* __restrict__ out) {
    int row = blockIdx.x;
    int t = threadIdx.x;
    const float* xr = x + (size_t)row * C_DIM;

    float v0 = xr[t], v1 = xr[t + 256], v2 = xr[t + 512];
    float s = v0 + v1 + v2;

    __shared__ float red[8];
    #pragma unroll
    for (int o = 16; o; o >>= 1) s += __shfl_xor_sync(0xFFFFFFFFu, s, o);
    if ((t & 31) == 0) red[t >> 5] = s;
    __syncthreads();
    if (t < 8) {
        float w = red[t];
        #pragma unroll
        for (int o = 4; o; o >>= 1) w += __shfl_xor_sync(0xFFu, w, o);
        if (t == 0) red[0] = w;
    }
    __syncthreads();
    float mean = red[0] * (1.0f / C_DIM);

    float d0 = v0 - mean, d1 = v1 - mean, d2 = v2 - mean;
    float sq = d0 * d0 + d1 * d1 + d2 * d2;
    __shared__ float red2[8];
    #pragma unroll
    for (int o = 16; o; o >>= 1) sq += __shfl_xor_sync(0xFFFFFFFFu, sq, o);
    if ((t & 31) == 0) red2[t >> 5] = sq;
    __syncthreads();
    if (t < 8) {
        float w = red2[t];
        #pragma unroll
        for (int o = 4; o; o >>= 1) w += __shfl_xor_sync(0xFFu, w, o);
        if (t == 0) red2[0] = w;
    }
    __syncthreads();
    float rstd = rsqrtf(red2[0] * (1.0f / C_DIM) + 1e-5f);

    float* orow = out + (size_t)row * C_DIM;
    orow[t]       = d0 * rstd * g[t]       + b[t];
    orow[t + 256] = d1 * rstd * g[t + 256] + b[t + 256];
    orow[t + 512] = d2 * rstd * g[t + 512] + b[t + 512];
}

// ---------------------------------------------------------------------------
// Generic fp32 GEMM: C[M,N] = A[M,K] @ B[K,N] + bias (+ residual)
// BM=BN=64, BK=16, 256 threads, 4x4 per thread.
// M,N,K all divisible by tile sizes here (no bounds checks).
// ---------------------------------------------------------------------------
template <bool RES>
__global__ void gemm64(const float* __restrict__ A,
                       const float* __restrict__ B,
                       const float* __restrict__ bias,
                       const float* __restrict__ res,
                       float* __restrict__ Cm,
                       int N, int K) {
    __shared__ float As[16][68];  // transposed: As[k][m], padded stride
    __shared__ float Bs[16][64];  // Bs[k][n]

    int tid = threadIdx.x;
    int tx = tid & 15, ty = tid >> 4;
    int bm = blockIdx.y * 64, bn = blockIdx.x * 64;

    const float* Ab = A + (size_t)bm * K;
    const float* Bb = B + bn;

    float acc[4][4] = {};

    for (int k0 = 0; k0 < K; k0 += 16) {
        #pragma unroll
        for (int i = 0; i < 4; i++) {
            int idx = tid + i * 256;           // 1024 elems
            int m = idx >> 4, k = idx & 15;
            As[k][m] = Ab[(size_t)m * K + k0 + k];
        }
        #pragma unroll
        for (int i = 0; i < 4; i++) {
            int idx = tid + i * 256;
            int k = idx >> 6, n = idx & 63;
            Bs[k][n] = Bb[(size_t)(k0 + k) * N + n];
        }
        __syncthreads();

        #pragma unroll
        for (int kk = 0; kk < 16; kk++) {
            float4 a4 = *(const float4*)&As[kk][ty * 4];
            float4 b4 = *(const float4*)&Bs[kk][tx * 4];
            float av[4] = {a4.x, a4.y, a4.z, a4.w};
            float bv[4] = {b4.x, b4.y, b4.z, b4.w};
            #pragma unroll
            for (int i = 0; i < 4; i++)
                #pragma unroll
                for (int j = 0; j < 4; j++)
                    acc[i][j] += av[i] * bv[j];
        }
        __syncthreads();
    }

    #pragma unroll
    for (int i = 0; i < 4; i++) {
        int row = bm + ty * 4 + i;
        #pragma unroll
        for (int j = 0; j < 4; j++) {
            int col = bn + tx * 4 + j;
            float v = acc[i][j] + bias[col];
            if (RES) v += res[(size_t)row * N + col];
            Cm[(size_t)row * N + col] = v;
        }
    }
}

// ---------------------------------------------------------------------------
// Flash attention (fp32, no mask). One CTA = 64 query rows of one (b,h).
// Streams K/V in 64-wide chunks with online softmax. scale = 768^-0.5.
// qkv layout per token row (2304): head h -> [h*192 + 0:64]=q, +64 k, +128 v.
// ---------------------------------------------------------------------------
__global__ void flash_kernel(const float* __restrict__ qkv,
                             float* __restrict__ out) {
    extern __shared__ float sm[];
    float (*Qs)[68] = (float(*)[68])(sm);             // Qs[d][m]
    float (*Ks)[68] = (float(*)[68])(sm + 64 * 68);   // Ks[d][n]
    float (*Vs)[68] = (float(*)[68])(sm + 2 * 64 * 68); // Vs[kk][d]
    float (*Ps)[68] = (float(*)[68])(sm + 3 * 64 * 68); // Ps[n][m]

    int tid = threadIdx.x;
    int tx = tid & 15, ty = tid >> 4;
    int m0 = blockIdx.x * 64;
    int h  = blockIdx.y;
    int bb = blockIdx.z;

    const float* base = qkv + (size_t)bb * T_SEQ * QKV_DIM + h * (3 * HD);

    // Load Q tile transposed (d-major)
    #pragma unroll
    for (int i = 0; i < 16; i++) {
        int idx = tid + i * 256;      // 4096 elems
        int m = idx >> 6, d = idx & 63;
        Qs[d][m] = base[(size_t)(m0 + m) * QKV_DIM + d];
    }

    float O[4][4] = {};
    float mrow[4] = {-1e30f, -1e30f, -1e30f, -1e30f};
    float lrow[4] = {};
    const float scale = 0.03608439182435161f;  // 768^-0.5

    for (int n0 = 0; n0 < T_SEQ; n0 += 64) {
        #pragma unroll
        for (int i = 0; i < 16; i++) {
            int idx = tid + i * 256;
            int n = idx >> 6, d = idx & 63;
            const float* krow = base + (size_t)(n0 + n) * QKV_DIM;
            Ks[d][n] = krow[64 + d];
            Vs[n][d] = krow[128 + d];
        }
        __syncthreads();

        // S tile = Q @ K^T
        float acc[4][4] = {};
        #pragma unroll 8
        for (int d = 0; d < 64; d++) {
            float4 a4 = *(const float4*)&Qs[d][ty * 4];
            float4 b4 = *(const float4*)&Ks[d][tx * 4];
            float av[4] = {a4.x, a4.y, a4.z, a4.w};
            float bv[4] = {b4.x, b4.y, b4.z, b4.w};
            #pragma unroll
            for (int i = 0; i < 4; i++)
                #pragma unroll
                for (int j = 0; j < 4; j++)
                    acc[i][j] += av[i] * bv[j];
        }
        #pragma unroll
        for (int i = 0; i < 4; i++)
            #pragma unroll
            for (int j = 0; j < 4; j++)
                acc[i][j] *= scale;

        // Online softmax update per owned row
        #pragma unroll
        for (int i = 0; i < 4; i++) {
            float mt = fmaxf(fmaxf(acc[i][0], acc[i][1]),
                             fmaxf(acc[i][2], acc[i][3]));
            #pragma unroll
            for (int o = 8; o; o >>= 1)
                mt = fmaxf(mt, __shfl_xor_sync(0xFFFFFFFFu, mt, o));
            float mnew = fmaxf(mrow[i], mt);
            float al = __expf(mrow[i] - mnew);
            float rs = 0.0f;
            #pragma unroll
            for (int j = 0; j < 4; j++) {
                float p = __expf(acc[i][j] - mnew);
                acc[i][j] = p;
                rs += p;
            }
            #pragma unroll
            for (int o = 8; o; o >>= 1)
                rs += __shfl_xor_sync(0xFFFFFFFFu, rs, o);
            lrow[i] = lrow[i] * al + rs;
            mrow[i] = mnew;
            #pragma unroll
            for (int j = 0; j < 4; j++) O[i][j] *= al;
        }

        // Store P transposed: Ps[n][m]
        #pragma unroll
        for (int i = 0; i < 4; i++)
            #pragma unroll
            for (int j = 0; j < 4; j++)
                Ps[tx * 4 + j][ty * 4 + i] = acc[i][j];
        __syncthreads();

        // O += P @ V
        #pragma unroll 8
        for (int kk = 0; kk < 64; kk++) {
            float4 a4 = *(const float4*)&Ps[kk][ty * 4];
            float4 b4 = *(const float4*)&Vs[kk][tx * 4];
            float av[4] = {a4.x, a4.y, a4.z, a4.w};
            float bv[4] = {b4.x, b4.y, b4.z, b4.w};
            #pragma unroll
            for (int i = 0; i < 4; i++)
                #pragma unroll
                for (int j = 0; j < 4; j++)
                    O[i][j] += av[i] * bv[j];
        }
        __syncthreads();
    }

    // Epilogue: normalize and scatter back to (B,T,C) with head offset
    #pragma unroll
    for (int i = 0; i < 4; i++) {
        float inv = 1.0f / lrow[i];
        int row = m0 + ty * 4 + i;
        float* orow = out + (size_t)(bb * T_SEQ + row) * C_DIM + h * HD;
        #pragma unroll
        for (int j = 0; j < 4; j++)
            orow[tx * 4 + j] = O[i][j] * inv;
    }
}

// ---------------------------------------------------------------------------
// Launch: two identical passes (attn applied twice, per reference)
// ---------------------------------------------------------------------------
static void run_pass(const float* x_in, const float* ln_g, const float* ln_b,
                     const float* w_attn, const float* b_attn,
                     const float* w_proj, const float* b_proj,
                     float* x_out,
                     float* hbuf, float* qkvbuf, float* attbuf) {
    ln_kernel<<<M_TOK, 256>>>(x_in, ln_g, ln_b, hbuf);

    dim3 gq(QKV_DIM / 64, M_TOK / 64);
    gemm64<false><<<gq, 256>>>(hbuf, w_attn, b_attn, nullptr, qkvbuf,
                               QKV_DIM, C_DIM);

    dim3 gf(T_SEQ / 64, N_HEAD, B_SZ);
    size_t smem = 4 * 64 * 68 * sizeof(float);
    flash_kernel<<<gf, 256, smem>>>(qkvbuf, attbuf);

    dim3 gp(C_DIM / 64, M_TOK / 64);
    gemm64<true><<<gp, 256>>>(attbuf, w_proj, b_proj, x_in, x_out,
                              C_DIM, C_DIM);
}

extern "C" void kernel_launch(void* const* d_in, const int* in_sizes, int n_in,
                              void* d_out, int out_size) {
    const float* x      = (const float*)d_in[0];
    const float* w_attn = (const float*)d_in[1];
    const float* b_attn = (const float*)d_in[2];
    const float* w_proj = (const float*)d_in[3];
    const float* b_proj = (const float*)d_in[4];
    const float* ln1_g  = (const float*)d_in[5];
    const float* ln1_b  = (const float*)d_in[6];
    const float* ln2_g  = (const float*)d_in[7];
    const float* ln2_b  = (const float*)d_in[8];
    float* out = (float*)d_out;

    // Opt-in smem for flash kernel (idempotent; safe to call every launch)
    cudaFuncSetAttribute(flash_kernel,
                         cudaFuncAttributeMaxDynamicSharedMemorySize,
                         (int)(4 * 64 * 68 * sizeof(float)));

    float *hbuf, *qkvbuf, *attbuf;
    cudaGetSymbolAddress((void**)&hbuf, g_h);
    cudaGetSymbolAddress((void**)&qkvbuf, g_qkv);
    cudaGetSymbolAddress((void**)&attbuf, g_att);

    // Pass 1: out = x + attn(LN1(x))
    run_pass(x, ln1_g, ln1_b, w_attn, b_attn, w_proj, b_proj,
             out, hbuf, qkvbuf, attbuf);
    // Pass 2: out = out + attn(LN2(out))   (residual aliases out: each elem
    // read exactly once by the thread that writes it)
    run_pass(out, ln2_g, ln2_b, w_attn, b_attn, w_proj, b_proj,
             out, hbuf, qkvbuf, attbuf);
}

// round 3
// speedup vs baseline: 2.9950x; 2.9950x over previous
#include <cuda_runtime.h>
#include <math.h>
#include <stdint.h>

#define B_SZ    4
#define T_SEQ   2048
#define C_DIM   768
#define QKV_DIM 2304
#define N_HEAD  12
#define HD      64
#define M_TOK   (B_SZ * T_SEQ)   // 8192

// Scratch (device globals: no allocation allowed)
__device__ float g_h[M_TOK * C_DIM];
__device__ float g_qkv[M_TOK * QKV_DIM];
__device__ float g_att[M_TOK * C_DIM];
__device__ float g_wT[QKV_DIM * C_DIM];   // w_attn^T  [N=2304, K=768]
__device__ float g_wpT[C_DIM * C_DIM];    // w_proj^T  [N=768,  K=768]

// ---------------------------------------------------------------------------
// tf32 helpers (plain sm_103 target: mma.sync is available, tcgen05 is NOT)
// ---------------------------------------------------------------------------
__device__ __forceinline__ uint32_t f2tf32(float x) {
    uint32_t u;
    asm("cvt.rna.tf32.f32 %0, %1;" : "=r"(u) : "f"(x));
    return u;
}

// D(16x8) += A(16x8) * B(8x8), tf32 in, fp32 accumulate.
// Thread layout (g = lane>>2, c = lane&3):
//   A: a0=[g][c] a1=[g+8][c] a2=[g][c+4] a3=[g+8][c+4]
//   B: b0=[k=c][n=g] b1=[k=c+4][n=g]
//   D: d0=[g][2c] d1=[g][2c+1] d2=[g+8][2c] d3=[g+8][2c+1]
__device__ __forceinline__ void mma8(float d[4], const uint32_t a[4],
                                     const uint32_t b[2]) {
    asm volatile(
        "mma.sync.aligned.m16n8k8.row.col.f32.tf32.tf32.f32 "
        "{%0,%1,%2,%3}, {%4,%5,%6,%7}, {%8,%9}, {%0,%1,%2,%3};"
        : "+f"(d[0]), "+f"(d[1]), "+f"(d[2]), "+f"(d[3])
        : "r"(a[0]), "r"(a[1]), "r"(a[2]), "r"(a[3]), "r"(b[0]), "r"(b[1]));
}

// ---------------------------------------------------------------------------
// LayerNorm: one block per row (768 cols), 256 threads x 3 elems
// ---------------------------------------------------------------------------
__global__ void ln_kernel(const float* __restrict__ x,
                          const float* __restrict__ g,
                          const float* __restrict__ b,
                          float* __restrict__ out) {
    int row = blockIdx.x;
    int t = threadIdx.x;
    const float* xr = x + (size_t)row * C_DIM;

    float v0 = xr[t], v1 = xr[t + 256], v2 = xr[t + 512];
    float s = v0 + v1 + v2;

    __shared__ float red[8];
    #pragma unroll
    for (int o = 16; o; o >>= 1) s += __shfl_xor_sync(0xFFFFFFFFu, s, o);
    if ((t & 31) == 0) red[t >> 5] = s;
    __syncthreads();
    if (t < 8) {
        float w = red[t];
        #pragma unroll
        for (int o = 4; o; o >>= 1) w += __shfl_xor_sync(0xFFu, w, o);
        if (t == 0) red[0] = w;
    }
    __syncthreads();
    float mean = red[0] * (1.0f / C_DIM);

    float d0 = v0 - mean, d1 = v1 - mean, d2 = v2 - mean;
    float sq = d0 * d0 + d1 * d1 + d2 * d2;
    __shared__ float red2[8];
    #pragma unroll
    for (int o = 16; o; o >>= 1) sq += __shfl_xor_sync(0xFFFFFFFFu, sq, o);
    if ((t & 31) == 0) red2[t >> 5] = sq;
    __syncthreads();
    if (t < 8) {
        float w = red2[t];
        #pragma unroll
        for (int o = 4; o; o >>= 1) w += __shfl_xor_sync(0xFFu, w, o);
        if (t == 0) red2[0] = w;
    }
    __syncthreads();
    float rstd = rsqrtf(red2[0] * (1.0f / C_DIM) + 1e-5f);

    float* orow = out + (size_t)row * C_DIM;
    orow[t]       = d0 * rstd * g[t]       + b[t];
    orow[t + 256] = d1 * rstd * g[t + 256] + b[t + 256];
    orow[t + 512] = d2 * rstd * g[t + 512] + b[t + 512];
}

// ---------------------------------------------------------------------------
// Weight transpose: W[K,N] (N contiguous) -> WT[N,K] (K contiguous)
// ---------------------------------------------------------------------------
__global__ void transpose_kn(const float* __restrict__ W, float* __restrict__ WT,
                             int K, int N) {
    __shared__ float t[32][33];
    int n0 = blockIdx.x * 32, k0 = blockIdx.y * 32;
    int x = threadIdx.x, y = threadIdx.y;
    #pragma unroll
    for (int i = 0; i < 32; i += 8)
        t[y + i][x] = W[(size_t)(k0 + y + i) * N + n0 + x];
    __syncthreads();
    #pragma unroll
    for (int i = 0; i < 32; i += 8)
        WT[(size_t)(n0 + y + i) * K + k0 + x] = t[x][y + i];
}

// ---------------------------------------------------------------------------
// tf32 mma.sync GEMM: C[M,N] = A[M,K] @ BT[N,K]^T + bias (+ residual)
// Tile 128x128x16, 256 threads = 8 warps (4 M x 2 N), warp tile 32x64.
// ---------------------------------------------------------------------------
#define GPITCH 20   // floats per smem row (16 data + 4 pad); conflict-free frags

template <bool RES>
__global__ void __launch_bounds__(256, 2)
gemm_mma(const float* __restrict__ A, const float* __restrict__ BT,
         const float* __restrict__ bias, const float* __restrict__ res,
         float* __restrict__ Cm, int N, int K) {
    __shared__ uint32_t As[128 * GPITCH];
    __shared__ uint32_t Bs[128 * GPITCH];

    int tid = threadIdx.x, lane = tid & 31, wid = tid >> 5;
    int g = lane >> 2, c = lane & 3;
    int wm = wid & 3, wn = wid >> 2;
    int bm = blockIdx.y * 128, bn = blockIdx.x * 128;

    const float* Ab = A + (size_t)bm * K;
    const float* Bb = BT + (size_t)bn * K;

    int r0 = tid >> 2;             // 0..63
    int c4 = (tid & 3) * 4;        // 0,4,8,12

    float acc[2][8][4] = {};
    float4 ra0, ra1, rb0, rb1;

    // preload iter 0
    ra0 = *(const float4*)(Ab + (size_t)r0 * K + c4);
    ra1 = *(const float4*)(Ab + (size_t)(r0 + 64) * K + c4);
    rb0 = *(const float4*)(Bb + (size_t)r0 * K + c4);
    rb1 = *(const float4*)(Bb + (size_t)(r0 + 64) * K + c4);

    int iters = K / 16;
    for (int it = 0; it < iters; ++it) {
        // stage current regs -> smem (tf32 rounded)
        uint4 ua0 = {f2tf32(ra0.x), f2tf32(ra0.y), f2tf32(ra0.z), f2tf32(ra0.w)};
        uint4 ua1 = {f2tf32(ra1.x), f2tf32(ra1.y), f2tf32(ra1.z), f2tf32(ra1.w)};
        uint4 ub0 = {f2tf32(rb0.x), f2tf32(rb0.y), f2tf32(rb0.z), f2tf32(rb0.w)};
        uint4 ub1 = {f2tf32(rb1.x), f2tf32(rb1.y), f2tf32(rb1.z), f2tf32(rb1.w)};
        *(uint4*)&As[r0 * GPITCH + c4]        = ua0;
        *(uint4*)&As[(r0 + 64) * GPITCH + c4] = ua1;
        *(uint4*)&Bs[r0 * GPITCH + c4]        = ub0;
        *(uint4*)&Bs[(r0 + 64) * GPITCH + c4] = ub1;
        __syncthreads();

        if (it + 1 < iters) {
            int ko = (it + 1) * 16;
            ra0 = *(const float4*)(Ab + (size_t)r0 * K + ko + c4);
            ra1 = *(const float4*)(Ab + (size_t)(r0 + 64) * K + ko + c4);
            rb0 = *(const float4*)(Bb + (size_t)r0 * K + ko + c4);
            rb1 = *(const float4*)(Bb + (size_t)(r0 + 64) * K + ko + c4);
        }

        #pragma unroll
        for (int ks = 0; ks < 2; ++ks) {
            int k = ks * 8;
            uint32_t af[2][4];
            #pragma unroll
            for (int mt = 0; mt < 2; ++mt) {
                int r = wm * 32 + mt * 16;
                af[mt][0] = As[(r + g) * GPITCH + k + c];
                af[mt][1] = As[(r + g + 8) * GPITCH + k + c];
                af[mt][2] = As[(r + g) * GPITCH + k + c + 4];
                af[mt][3] = As[(r + g + 8) * GPITCH + k + c + 4];
            }
            #pragma unroll
            for (int nt = 0; nt < 8; ++nt) {
                int n = wn * 64 + nt * 8 + g;
                uint32_t bf[2];
                bf[0] = Bs[n * GPITCH + k + c];
                bf[1] = Bs[n * GPITCH + k + c + 4];
                mma8(acc[0][nt], af[0], bf);
                mma8(acc[1][nt], af[1], bf);
            }
        }
        if (it + 1 < iters) __syncthreads();
    }

    // epilogue: d0,d1 -> (row, 2c), (row, 2c+1); d2,d3 -> row+8
    #pragma unroll
    for (int mt = 0; mt < 2; ++mt) {
        int r = bm + wm * 32 + mt * 16 + g;
        #pragma unroll
        for (int nt = 0; nt < 8; ++nt) {
            int col = bn + wn * 64 + nt * 8 + 2 * c;
            float2 bi = *(const float2*)(bias + col);
            float2 o0 = {acc[mt][nt][0] + bi.x, acc[mt][nt][1] + bi.y};
            float2 o1 = {acc[mt][nt][2] + bi.x, acc[mt][nt][3] + bi.y};
            size_t i0 = (size_t)r * N + col;
            size_t i1 = (size_t)(r + 8) * N + col;
            if (RES) {
                float2 q0 = *(const float2*)(res + i0);
                float2 q1 = *(const float2*)(res + i1);
                o0.x += q0.x; o0.y += q0.y;
                o1.x += q1.x; o1.y += q1.y;
            }
            *(float2*)(Cm + i0) = o0;
            *(float2*)(Cm + i1) = o1;
        }
    }
}

// ---------------------------------------------------------------------------
// Flash attention with tf32 mma.sync. One CTA = 64 q-rows of one (b,h).
// 128 threads = 4 warps, each warp owns 16 rows (no cross-warp softmax).
// S = Q@K^T (64x64x64), online softmax on accum frags, P via smem, O += P@V.
// ---------------------------------------------------------------------------
#define FP_QK 68   // pitch for Qs/Ks/Ps (rows of 64 + pad)
#define FP_V  72   // pitch for Vs (conflict-free k-major B-frag reads)
#define FLASH_SMEM ((3 * 64 * FP_QK + 64 * FP_V) * 4)

__global__ void __launch_bounds__(128)
flash_mma(const float* __restrict__ qkv, float* __restrict__ out) {
    extern __shared__ uint32_t sm4[];
    uint32_t* Qs = sm4;                        // [64][FP_QK]
    uint32_t* Ks = sm4 + 64 * FP_QK;           // [64][FP_QK]
    uint32_t* Ps = sm4 + 2 * 64 * FP_QK;       // [64][FP_QK]
    uint32_t* Vs = sm4 + 3 * 64 * FP_QK;       // [64][FP_V] (seq-major)

    int tid = threadIdx.x, lane = tid & 31, wid = tid >> 5;
    int g = lane >> 2, c = lane & 3;
    int rb = wid * 16;
    int m0 = blockIdx.x * 64;
    int h  = blockIdx.y;
    int bb = blockIdx.z;

    const float* base = qkv + (size_t)bb * T_SEQ * QKV_DIM + h * (3 * HD);

    // Load Q tile (64x64) -> Qs[m][d], tf32 rounded
    #pragma unroll
    for (int i = 0; i < 8; i++) {
        int slot = tid + i * 128;        // 1024 float4 slots
        int r = slot >> 4, cc = (slot & 15) * 4;
        float4 v = *(const float4*)(base + (size_t)(m0 + r) * QKV_DIM + cc);
        uint4 u = {f2tf32(v.x), f2tf32(v.y), f2tf32(v.z), f2tf32(v.w)};
        *(uint4*)&Qs[r * FP_QK + cc] = u;
    }

    float o[8][4] = {};
    float mrow0 = -1e30f, mrow1 = -1e30f;
    float lrow0 = 0.0f, lrow1 = 0.0f;
    const float scale = 0.03608439182435161f;   // 768^-0.5

    for (int n0 = 0; n0 < T_SEQ; n0 += 64) {
        // Load K,V tiles (64x64 each)
        #pragma unroll
        for (int i = 0; i < 8; i++) {
            int slot = tid + i * 128;
            int r = slot >> 4, cc = (slot & 15) * 4;
            const float* krow = base + (size_t)(n0 + r) * QKV_DIM;
            float4 kv = *(const float4*)(krow + 64 + cc);
            float4 vv = *(const float4*)(krow + 128 + cc);
            uint4 uk = {f2tf32(kv.x), f2tf32(kv.y), f2tf32(kv.z), f2tf32(kv.w)};
            uint4 uv = {f2tf32(vv.x), f2tf32(vv.y), f2tf32(vv.z), f2tf32(vv.w)};
            *(uint4*)&Ks[r * FP_QK + cc] = uk;
            *(uint4*)&Vs[r * FP_V + cc]  = uv;
        }
        __syncthreads();

        // S = Q @ K^T for this warp's 16 rows
        float s[8][4] = {};
        #pragma unroll
        for (int kt = 0; kt < 8; ++kt) {
            int k = kt * 8;
            uint32_t af[4];
            af[0] = Qs[(rb + g) * FP_QK + k + c];
            af[1] = Qs[(rb + g + 8) * FP_QK + k + c];
            af[2] = Qs[(rb + g) * FP_QK + k + c + 4];
            af[3] = Qs[(rb + g + 8) * FP_QK + k + c + 4];
            #pragma unroll
            for (int nt = 0; nt < 8; ++nt) {
                uint32_t bf[2];
                bf[0] = Ks[(nt * 8 + g) * FP_QK + k + c];
                bf[1] = Ks[(nt * 8 + g) * FP_QK + k + c + 4];
                mma8(s[nt], af, bf);
            }
        }

        // scale + row maxes (rows g and g+8; quad lanes own all 64 cols)
        float mt0 = -1e30f, mt1 = -1e30f;
        #pragma unroll
        for (int nt = 0; nt < 8; ++nt) {
            s[nt][0] *= scale; s[nt][1] *= scale;
            s[nt][2] *= scale; s[nt][3] *= scale;
            mt0 = fmaxf(mt0, fmaxf(s[nt][0], s[nt][1]));
            mt1 = fmaxf(mt1, fmaxf(s[nt][2], s[nt][3]));
        }
        mt0 = fmaxf(mt0, __shfl_xor_sync(0xFFFFFFFFu, mt0, 1));
        mt0 = fmaxf(mt0, __shfl_xor_sync(0xFFFFFFFFu, mt0, 2));
        mt1 = fmaxf(mt1, __shfl_xor_sync(0xFFFFFFFFu, mt1, 1));
        mt1 = fmaxf(mt1, __shfl_xor_sync(0xFFFFFFFFu, mt1, 2));

        float mnew0 = fmaxf(mrow0, mt0);
        float mnew1 = fmaxf(mrow1, mt1);
        float al0 = __expf(mrow0 - mnew0);
        float al1 = __expf(mrow1 - mnew1);

        float rs0 = 0.0f, rs1 = 0.0f;
        #pragma unroll
        for (int nt = 0; nt < 8; ++nt) {
            float p0 = __expf(s[nt][0] - mnew0);
            float p1 = __expf(s[nt][1] - mnew0);
            float p2 = __expf(s[nt][2] - mnew1);
            float p3 = __expf(s[nt][3] - mnew1);
            s[nt][0] = p0; s[nt][1] = p1; s[nt][2] = p2; s[nt][3] = p3;
            rs0 += p0 + p1; rs1 += p2 + p3;
        }
        rs0 += __shfl_xor_sync(0xFFFFFFFFu, rs0, 1);
        rs0 += __shfl_xor_sync(0xFFFFFFFFu, rs0, 2);
        rs1 += __shfl_xor_sync(0xFFFFFFFFu, rs1, 1);
        rs1 += __shfl_xor_sync(0xFFFFFFFFu, rs1, 2);

        lrow0 = lrow0 * al0 + rs0;
        lrow1 = lrow1 * al1 + rs1;
        mrow0 = mnew0; mrow1 = mnew1;

        #pragma unroll
        for (int nt = 0; nt < 8; ++nt) {
            o[nt][0] *= al0; o[nt][1] *= al0;
            o[nt][2] *= al1; o[nt][3] *= al1;
        }

        // P -> smem (accum layout -> A-operand layout via smem round trip)
        #pragma unroll
        for (int nt = 0; nt < 8; ++nt) {
            int col = nt * 8 + 2 * c;
            Ps[(rb + g) * FP_QK + col]     = f2tf32(s[nt][0]);
            Ps[(rb + g) * FP_QK + col + 1] = f2tf32(s[nt][1]);
            Ps[(rb + g + 8) * FP_QK + col]     = f2tf32(s[nt][2]);
            Ps[(rb + g + 8) * FP_QK + col + 1] = f2tf32(s[nt][3]);
        }
        __syncwarp();   // warp reads only its own 16 rows of Ps

        // O += P @ V   (K dim = seq 64, N dim = headdim 64)
        #pragma unroll
        for (int kt = 0; kt < 8; ++kt) {
            int k = kt * 8;
            uint32_t af[4];
            af[0] = Ps[(rb + g) * FP_QK + k + c];
            af[1] = Ps[(rb + g + 8) * FP_QK + k + c];
            af[2] = Ps[(rb + g) * FP_QK + k + c + 4];
            af[3] = Ps[(rb + g + 8) * FP_QK + k + c + 4];
            #pragma unroll
            for (int nt = 0; nt < 8; ++nt) {
                uint32_t bf[2];
                bf[0] = Vs[(k + c) * FP_V + nt * 8 + g];
                bf[1] = Vs[(k + c + 4) * FP_V + nt * 8 + g];
                mma8(o[nt], af, bf);
            }
        }
        __syncthreads();   // before next K/V overwrite
    }

    // epilogue: normalize, scatter to (B,T,C) at head offset
    float inv0 = 1.0f / lrow0;
    float inv1 = 1.0f / lrow1;
    int row0 = m0 + rb + g;
    int row1 = row0 + 8;
    float* ob = out + (size_t)bb * T_SEQ * C_DIM + h * HD;
    #pragma unroll
    for (int nt = 0; nt < 8; ++nt) {
        int col = nt * 8 + 2 * c;
        float2 v0 = {o[nt][0] * inv0, o[nt][1] * inv0};
        float2 v1 = {o[nt][2] * inv1, o[nt][3] * inv1};
        *(float2*)(ob + (size_t)row0 * C_DIM + col) = v0;
        *(float2*)(ob + (size_t)row1 * C_DIM + col) = v1;
    }
}

// ---------------------------------------------------------------------------
// Launch
// ---------------------------------------------------------------------------
static void run_pass(const float* x_in, const float* ln_g, const float* ln_b,
                     const float* wT, const float* b_attn,
                     const float* wpT, const float* b_proj,
                     float* x_out,
                     float* hbuf, float* qkvbuf, float* attbuf) {
    ln_kernel<<<M_TOK, 256>>>(x_in, ln_g, ln_b, hbuf);

    dim3 gq(QKV_DIM / 128, M_TOK / 128);
    gemm_mma<false><<<gq, 256>>>(hbuf, wT, b_attn, nullptr, qkvbuf,
                                 QKV_DIM, C_DIM);

    dim3 gf(T_SEQ / 64, N_HEAD, B_SZ);
    flash_mma<<<gf, 128, FLASH_SMEM>>>(qkvbuf, attbuf);

    dim3 gp(C_DIM / 128, M_TOK / 128);
    gemm_mma<true><<<gp, 256>>>(attbuf, wpT, b_proj, x_in, x_out,
                                C_DIM, C_DIM);
}

extern "C" void kernel_launch(void* const* d_in, const int* in_sizes, int n_in,
                              void* d_out, int out_size) {
    const float* x      = (const float*)d_in[0];
    const float* w_attn = (const float*)d_in[1];
    const float* b_attn = (const float*)d_in[2];
    const float* w_proj = (const float*)d_in[3];
    const float* b_proj = (const float*)d_in[4];
    const float* ln1_g  = (const float*)d_in[5];
    const float* ln1_b  = (const float*)d_in[6];
    const float* ln2_g  = (const float*)d_in[7];
    const float* ln2_b  = (const float*)d_in[8];
    float* out = (float*)d_out;

    cudaFuncSetAttribute(flash_mma,
                         cudaFuncAttributeMaxDynamicSharedMemorySize,
                         FLASH_SMEM);

    float *hbuf, *qkvbuf, *attbuf, *wT, *wpT;
    cudaGetSymbolAddress((void**)&hbuf, g_h);
    cudaGetSymbolAddress((void**)&qkvbuf, g_qkv);
    cudaGetSymbolAddress((void**)&attbuf, g_att);
    cudaGetSymbolAddress((void**)&wT, g_wT);
    cudaGetSymbolAddress((void**)&wpT, g_wpT);

    // Weight transposes (repeated each replay; cheap)
    dim3 tb(32, 8);
    transpose_kn<<<dim3(QKV_DIM / 32, C_DIM / 32), tb>>>(w_attn, wT, C_DIM, QKV_DIM);
    transpose_kn<<<dim3(C_DIM / 32, C_DIM / 32), tb>>>(w_proj, wpT, C_DIM, C_DIM);

    run_pass(x, ln1_g, ln1_b, wT, b_attn, wpT, b_proj,
             out, hbuf, qkvbuf, attbuf);
    run_pass(out, ln2_g, ln2_b, wT, b_attn, wpT, b_proj,
             out, hbuf, qkvbuf, attbuf);
}